// round 2
// baseline (speedup 1.0000x reference)
#include <cuda_runtime.h>

#define H_IMG 192
#define W_IMG 320
#define P_TOT (H_IMG*W_IMG)   /* 61440 */
#define BATCH 2
#define NCH   64
#define PITCH 264
#define MTILE 64
#define NTHR  256
#define TILES_PER_IMG (P_TOT/MTILE)   /* 960 */
#define NTILES (TILES_PER_IMG*3*BATCH) /* 5760 */

// Transposed, K-padded weights: Wt[l][k][n]
// sizes (Kpad*N): 72*64, 64*64, 64*256, 256*256, 256*256, 256*64
static __device__ float g_wt[172544];

__global__ void wt_transpose_kernel(const float* __restrict__ w0, const float* __restrict__ w1,
                                    const float* __restrict__ w2, const float* __restrict__ w3,
                                    const float* __restrict__ w4, const float* __restrict__ w5)
{
    const int K [6] = {65,64,64,256,256,256};
    const int KP[6] = {72,64,64,256,256,256};
    const int N [6] = {64,64,256,256,256,64};
    const int OFF[6]= {0,4608,8704,25088,90624,156160};
    int l = blockIdx.y;
    const float* w = (l==0)?w0 : (l==1)?w1 : (l==2)?w2 : (l==3)?w3 : (l==4)?w4 : w5;
    int total = KP[l]*N[l];
    for (int idx = blockIdx.x*blockDim.x + threadIdx.x; idx < total; idx += gridDim.x*blockDim.x) {
        int k = idx / N[l];
        int n = idx - k*N[l];
        g_wt[OFF[l] + idx] = (k < K[l]) ? w[n*K[l] + k] : 0.0f;
    }
}

__device__ __forceinline__ void fma2(unsigned long long &acc, unsigned long long a, unsigned long long b){
    asm("fma.rn.f32x2 %0, %1, %2, %0;" : "+l"(acc) : "l"(a), "l"(b));
}
__device__ __forceinline__ unsigned long long dup2(float x){
    unsigned long long r; asm("mov.b64 %0, {%1, %1};" : "=l"(r) : "f"(x)); return r;
}
__device__ __forceinline__ void unpk(unsigned long long v, float &x, float &y){
    asm("mov.b64 {%0, %1}, %2;" : "=f"(x), "=f"(y) : "l"(v));
}
__device__ __forceinline__ void cp16(unsigned int dst, const float* src){
    asm volatile("cp.async.cg.shared.global [%0], [%1], 16;" :: "r"(dst), "l"(src));
}
__device__ __forceinline__ void cp_commit(){ asm volatile("cp.async.commit_group;"); }
__device__ __forceinline__ void cp_wait0(){ asm volatile("cp.async.wait_group 0;"); }

// One dense layer on the 64-row tile. aIn: [64][PITCH] smem, aOut: [64][PITCH] smem.
// Wt (global, transposed) layout [Kpad][Nl]. TN = per-thread output columns (8 or 2).
template<int TN, bool LAST>
__device__ __forceinline__ void run_layer(const float* __restrict__ aIn, float* __restrict__ aOut,
                                          float* wbuf, const float* __restrict__ sb_bias,
                                          const float* __restrict__ wt, int Kpad, int Nl, int tid)
{
    const int r  = tid >> 5;    // row group (8 rows each)
    const int cg = tid & 31;    // column group (TN cols each)

    unsigned long long acc[8][TN/2];
#pragma unroll
    for (int i = 0; i < 8; i++)
#pragma unroll
        for (int j = 0; j < TN/2; j++) acc[i][j] = 0ull;

    const int nkc   = Kpad >> 3;
    const int words = 2*Nl;  // float4s per 8xN chunk
    unsigned int wb_s0 = (unsigned int)__cvta_generic_to_shared(wbuf);

    // stage chunk 0
    for (int i = tid; i < words; i += NTHR) cp16(wb_s0 + i*16, wt + i*4);
    cp_commit();

    int buf = 0;
    for (int kc = 0; kc < nkc; kc++){
        cp_wait0();
        __syncthreads();
        if (kc + 1 < nkc){
            const float* src = wt + (size_t)(kc+1)*8*Nl;
            unsigned int dst = wb_s0 + (buf^1)*2048*4;
            for (int i = tid; i < words; i += NTHR) cp16(dst + i*16, src + i*4);
            cp_commit();
        }
        const float* wbp = wbuf + buf*2048;
        const int k0 = kc*8;
#pragma unroll
        for (int kk = 0; kk < 8; kk += 4){
            float4 a4[8];
#pragma unroll
            for (int i = 0; i < 8; i++)
                a4[i] = *(const float4*)(aIn + (r*8+i)*PITCH + k0 + kk);
#pragma unroll
            for (int t = 0; t < 4; t++){
                const float* wr = wbp + (kk+t)*Nl + cg*TN;
                if (TN == 8){
                    ulonglong2 wA = *(const ulonglong2*)(wr);
                    ulonglong2 wB = *(const ulonglong2*)(wr + 4);
#pragma unroll
                    for (int i = 0; i < 8; i++){
                        float av = (t==0) ? a4[i].x : (t==1) ? a4[i].y : (t==2) ? a4[i].z : a4[i].w;
                        unsigned long long aa = dup2(av);
                        fma2(acc[i][0], aa, wA.x);
                        fma2(acc[i][1], aa, wA.y);
                        fma2(acc[i][2], aa, wB.x);
                        fma2(acc[i][3], aa, wB.y);
                    }
                } else {
                    unsigned long long wv = *(const unsigned long long*)(wr);
#pragma unroll
                    for (int i = 0; i < 8; i++){
                        float av = (t==0) ? a4[i].x : (t==1) ? a4[i].y : (t==2) ? a4[i].z : a4[i].w;
                        fma2(acc[i][0], dup2(av), wv);
                    }
                }
            }
        }
        buf ^= 1;
        __syncthreads();
    }

    // epilogue: bias + sin(30x) (except last layer), write to aOut
#pragma unroll
    for (int i = 0; i < 8; i++){
        int m = r*8 + i;
#pragma unroll
        for (int jj = 0; jj < TN/2; jj++){
            float x, y; unpk(acc[i][jj], x, y);
            int n = cg*TN + 2*jj;
            x += sb_bias[n];
            y += sb_bias[n+1];
            if (!LAST){ x = __sinf(30.0f*x); y = __sinf(30.0f*y); }
            float2 v; v.x = x; v.y = y;
            *(float2*)(aOut + m*PITCH + n) = v;
        }
    }
    __syncthreads();
}

__global__ void __launch_bounds__(NTHR, 1)
mlp_kernel(const float* __restrict__ feat, const float* __restrict__ times,
           const float* __restrict__ b0, const float* __restrict__ b1,
           const float* __restrict__ b2, const float* __restrict__ b3,
           const float* __restrict__ b4, const float* __restrict__ b5,
           float* __restrict__ out)
{
    extern __shared__ float sm[];
    float* actA = sm;                       // 64*264
    float* actB = actA + MTILE*PITCH;       // 64*264
    float* wbuf = actB + MTILE*PITCH;       // 2*2048
    float* sb   = wbuf + 2*2048;            // 960 biases

    const int tid = threadIdx.x;

    // biases into smem (offsets 0,64,128,384,640,896)
    if (tid < 64){ sb[tid] = b0[tid]; sb[64+tid] = b1[tid]; sb[896+tid] = b5[tid]; }
    sb[128+tid] = b2[tid];
    sb[384+tid] = b3[tid];
    sb[640+tid] = b4[tid];

    const int tile = blockIdx.x;
    const int img  = tile / TILES_PER_IMG;     // = c*BATCH + b
    const int pt   = tile - img*TILES_PER_IMG;
    const int p0   = pt * MTILE;
    const int c    = img >> 1;
    const int b    = img & 1;
    const float tval = times[c];

    // Load feat tile transposed: actA[m][ch] = feat[b][ch][p0+m]
    {
        int chb = tid >> 4;          // 0..15
        int m0  = (tid & 15) * 4;    // 0..60
#pragma unroll
        for (int pass = 0; pass < 4; pass++){
            int ch = pass*16 + chb;
            float4 v = *(const float4*)(feat + (size_t)(b*NCH + ch)*P_TOT + p0 + m0);
            actA[(m0+0)*PITCH + ch] = v.x;
            actA[(m0+1)*PITCH + ch] = v.y;
            actA[(m0+2)*PITCH + ch] = v.z;
            actA[(m0+3)*PITCH + ch] = v.w;
        }
    }
    // time feature + zero pad to K=72
    for (int m = tid; m < MTILE; m += NTHR){
        actA[m*PITCH + 64] = tval;
#pragma unroll
        for (int k = 65; k < 72; k++) actA[m*PITCH + k] = 0.0f;
    }
    __syncthreads();

    run_layer<2,false>(actA, actB, wbuf, sb +   0, g_wt +      0,  72,  64, tid);
    run_layer<2,false>(actB, actA, wbuf, sb +  64, g_wt +   4608,  64,  64, tid);
    run_layer<8,false>(actA, actB, wbuf, sb + 128, g_wt +   8704,  64, 256, tid);
    run_layer<8,false>(actB, actA, wbuf, sb + 384, g_wt +  25088, 256, 256, tid);
    run_layer<8,false>(actA, actB, wbuf, sb + 640, g_wt +  90624, 256, 256, tid);
    run_layer<2,true >(actB, actA, wbuf, sb + 896, g_wt + 156160, 256,  64, tid);
    // result in actA: [m][o]

    // Store: out[((c*B+b)*64 + o)*P + p0 + m], coalesced over m
    {
        const float* res = actA;
        size_t obase = (size_t)img * 64 * P_TOT + p0;
        int o  = tid >> 2;         // 0..63
        int ms = (tid & 3) * 16;   // 0,16,32,48
#pragma unroll
        for (int mm = 0; mm < 16; mm += 4){
            int m = ms + mm;
            float4 v;
            v.x = res[(m+0)*PITCH + o];
            v.y = res[(m+1)*PITCH + o];
            v.z = res[(m+2)*PITCH + o];
            v.w = res[(m+3)*PITCH + o];
            *(float4*)(out + obase + (size_t)o*P_TOT + m) = v;
        }
    }
}

extern "C" void kernel_launch(void* const* d_in, const int* in_sizes, int n_in,
                              void* d_out, int out_size)
{
    const float* feat  = (const float*)d_in[0];
    const float* times = (const float*)d_in[1];
    const float* w0 = (const float*)d_in[2];
    const float* b0 = (const float*)d_in[3];
    const float* w1 = (const float*)d_in[4];
    const float* b1 = (const float*)d_in[5];
    const float* w2 = (const float*)d_in[6];
    const float* b2 = (const float*)d_in[7];
    const float* w3 = (const float*)d_in[8];
    const float* b3 = (const float*)d_in[9];
    const float* w4 = (const float*)d_in[10];
    const float* b4 = (const float*)d_in[11];
    const float* w5 = (const float*)d_in[12];
    const float* b5 = (const float*)d_in[13];
    float* out = (float*)d_out;

    const int smem_bytes = (MTILE*PITCH*2 + 2*2048 + 960) * 4;  // 155392
    cudaFuncSetAttribute(mlp_kernel, cudaFuncAttributeMaxDynamicSharedMemorySize, smem_bytes);

    wt_transpose_kernel<<<dim3(256,6), 256>>>(w0,w1,w2,w3,w4,w5);
    mlp_kernel<<<NTILES, NTHR, smem_bytes>>>(feat, times, b0,b1,b2,b3,b4,b5, out);
}

// round 5
// speedup vs baseline: 3.6690x; 3.6690x over previous
#include <cuda_runtime.h>
#include <cuda_bf16.h>

#define P_TOT   61440
#define MROWS   128
#define NTHR    256
#define TILES_PER_IMG 480
#define NCTA    2880
#define W0S     30.0f

/* smem map (bytes) */
#define A_HI    0          /* 128 x 256 bf16, swizzled, 64KB */
#define A_LO    65536      /* 64KB */
#define WB0     131072     /* 32KB */
#define WB1     163840     /* 32KB */
#define SB_OFF  196608     /* 960 floats */
#define SMEM_TOT 200448

/* weights, hi/lo split, per-chunk layout: [hi: N x 32 bf16 swz][lo: same] */
static __device__ __align__(16) __nv_bfloat16 g_w[348160];

__global__ void prep_kernel(const float* __restrict__ w0, const float* __restrict__ w1,
                            const float* __restrict__ w2, const float* __restrict__ w3,
                            const float* __restrict__ w4, const float* __restrict__ w5)
{
    const int K[6]    = {65,64,64,256,256,256};
    const int N[6]    = {64,64,256,256,256,64};
    const int NCHK[6] = {3,2,2,8,8,8};
    const int GOFF[6] = {0,12288,20480,53248,184320,315392};
    int l = blockIdx.y;
    const float* w = (l==0)?w0:(l==1)?w1:(l==2)?w2:(l==3)?w3:(l==4)?w4:w5;
    int Nl = N[l], Kl = K[l];
    int total = NCHK[l]*Nl*32;
    for (int idx = blockIdx.x*blockDim.x + threadIdx.x; idx < total; idx += gridDim.x*blockDim.x){
        int kin = idx & 31;
        int n   = (idx >> 5) % Nl;
        int c   = idx / (32*Nl);
        int k   = c*32 + kin;
        float v = (k < Kl) ? w[n*Kl + k] : 0.0f;
        __nv_bfloat16 h  = __float2bfloat16(v);
        __nv_bfloat16 lo = __float2bfloat16(v - __bfloat162float(h));
        /* within chunk: row n (64B), 16B-chunk swizzle c16' = c16 ^ ((n>>1)&3) */
        int eoff = n*32 + ((((kin>>3) ^ ((n>>1)&3)) << 3) | (kin & 7));
        int base = GOFF[l] + c*(Nl*64);
        g_w[base + eoff]        = h;
        g_w[base + Nl*32 + eoff] = lo;
    }
}

/* ---------------- helpers ---------------- */
__device__ __forceinline__ unsigned s2u(const void* p){
    unsigned a;
    asm("{ .reg .u64 t; cvta.to.shared.u64 t, %1; cvt.u32.u64 %0, t; }" : "=r"(a) : "l"(p));
    return a;
}
__device__ __forceinline__ void cp16(unsigned dst, const void* src){
    asm volatile("cp.async.cg.shared.global [%0], [%1], 16;" :: "r"(dst), "l"(src));
}
__device__ __forceinline__ void cp_commit(){ asm volatile("cp.async.commit_group;"); }
__device__ __forceinline__ void cp_wait0(){ asm volatile("cp.async.wait_group 0;"); }
__device__ __forceinline__ void stage(unsigned dst, const char* src, int bytes, int tid){
    for (int i = tid*16; i < bytes; i += NTHR*16) cp16(dst + i, src + i);
}
__device__ __forceinline__ void ldmx4(unsigned* r, unsigned addr){
    asm volatile("ldmatrix.sync.aligned.m8n8.x4.shared.b16 {%0,%1,%2,%3}, [%4];"
        : "=r"(r[0]), "=r"(r[1]), "=r"(r[2]), "=r"(r[3]) : "r"(addr));
}
__device__ __forceinline__ void mma_bf16(float& c0, float& c1, float& c2, float& c3,
                                         unsigned a0, unsigned a1, unsigned a2, unsigned a3,
                                         unsigned b0, unsigned b1){
    asm volatile("mma.sync.aligned.m16n8k16.row.col.f32.bf16.bf16.f32 "
        "{%0,%1,%2,%3}, {%4,%5,%6,%7}, {%8,%9}, {%0,%1,%2,%3};"
        : "+f"(c0), "+f"(c1), "+f"(c2), "+f"(c3)
        : "r"(a0), "r"(a1), "r"(a2), "r"(a3), "r"(b0), "r"(b1));
}
__device__ __forceinline__ unsigned pack_bf2(float hi_val, float lo_val){
    unsigned r;  /* d.lo = lo_val, d.hi = hi_val */
    asm("cvt.rn.bf16x2.f32 %0, %1, %2;" : "=r"(r) : "f"(hi_val), "f"(lo_val));
    return r;
}
__device__ __forceinline__ float bflo(unsigned u){ return __bfloat162float(((__nv_bfloat162*)&u)->x); }
__device__ __forceinline__ float bfhi(unsigned u){ return __bfloat162float(((__nv_bfloat162*)&u)->y); }

/* one dense layer; A in smem (hi/lo, swizzled), updated in place by epilogue */
template<int NFRAG, bool LAST>
__device__ __forceinline__ void do_layer(unsigned smb, char* smp,
    const char* gw, int nchk, int chunk_bytes, const float* sbL,
    const char* gw_next, int next_bytes, int& buf,
    int tid, int rowbase, int nb, float* outp)
{
    const int lane  = tid & 31;
    const int gid   = lane >> 2, tig = lane & 3;
    const int row_a = (lane & 7) + ((lane >> 3) & 1)*8;
    const int ca    = lane >> 4;
    const int n_off = (lane & 7) + (lane >> 4)*8;
    const int cb    = (lane >> 3) & 1;
    const int NLOC  = chunk_bytes >> 7;

    float acc[2][NFRAG][4];
#pragma unroll
    for (int i = 0; i < 2; i++)
#pragma unroll
        for (int j = 0; j < NFRAG; j++)
#pragma unroll
            for (int q = 0; q < 4; q++) acc[i][j][q] = 0.0f;

    int cur = buf;
    for (int c = 0; c < nchk; c++){
        cp_wait0();
        __syncthreads();
        if (c + 1 < nchk){
            stage(smb + (cur ? WB0 : WB1), gw + (size_t)(c+1)*chunk_bytes, chunk_bytes, tid);
            cp_commit();
        }
        unsigned wb  = smb + (cur ? WB1 : WB0);
        unsigned wlo = wb + (unsigned)(NLOC*64);
#pragma unroll
        for (int s = 0; s < 2; s++){
            const int ks = c*2 + s;
            unsigned ah[2][4], al[2][4];
#pragma unroll
            for (int mt = 0; mt < 2; mt++){
                int row = rowbase + mt*16 + row_a;
                unsigned off = (unsigned)(row*512) + (unsigned)((((ks*2 + ca) ^ (row & 7))) << 4);
                ldmx4(ah[mt], smb + A_HI + off);
                ldmx4(al[mt], smb + A_LO + off);
            }
#pragma unroll
            for (int np = 0; np < NFRAG/2; np++){
                int n = nb + np*16 + n_off;
                unsigned off = (unsigned)(n*64) + (unsigned)((((2*s + cb) ^ ((n >> 1) & 3))) << 4);
                unsigned bh[4], bl[4];
                ldmx4(bh, wb + off);
                ldmx4(bl, wlo + off);
#pragma unroll
                for (int mt = 0; mt < 2; mt++){
                    mma_bf16(acc[mt][2*np][0],acc[mt][2*np][1],acc[mt][2*np][2],acc[mt][2*np][3],
                             ah[mt][0],ah[mt][1],ah[mt][2],ah[mt][3], bh[0],bh[1]);
                    mma_bf16(acc[mt][2*np][0],acc[mt][2*np][1],acc[mt][2*np][2],acc[mt][2*np][3],
                             al[mt][0],al[mt][1],al[mt][2],al[mt][3], bh[0],bh[1]);
                    mma_bf16(acc[mt][2*np][0],acc[mt][2*np][1],acc[mt][2*np][2],acc[mt][2*np][3],
                             ah[mt][0],ah[mt][1],ah[mt][2],ah[mt][3], bl[0],bl[1]);
                    mma_bf16(acc[mt][2*np+1][0],acc[mt][2*np+1][1],acc[mt][2*np+1][2],acc[mt][2*np+1][3],
                             ah[mt][0],ah[mt][1],ah[mt][2],ah[mt][3], bh[2],bh[3]);
                    mma_bf16(acc[mt][2*np+1][0],acc[mt][2*np+1][1],acc[mt][2*np+1][2],acc[mt][2*np+1][3],
                             al[mt][0],al[mt][1],al[mt][2],al[mt][3], bh[2],bh[3]);
                    mma_bf16(acc[mt][2*np+1][0],acc[mt][2*np+1][1],acc[mt][2*np+1][2],acc[mt][2*np+1][3],
                             ah[mt][0],ah[mt][1],ah[mt][2],ah[mt][3], bl[2],bl[3]);
                }
            }
        }
        cur ^= 1;
    }
    buf = cur;
    __syncthreads();           /* all A reads done before epilogue overwrites */
    if (gw_next){
        stage(smb + (cur ? WB1 : WB0), gw_next, next_bytes, tid);
        cp_commit();
    }

#pragma unroll
    for (int mt = 0; mt < 2; mt++){
#pragma unroll
        for (int nf = 0; nf < NFRAG; nf++){
            int n = nb + nf*8 + 2*tig;
            float bx = sbL[n], by = sbL[n+1];
            int r0 = rowbase + mt*16 + gid;
            if (!LAST){
                float v0 = __sinf(W0S*(acc[mt][nf][0] + bx));
                float v1 = __sinf(W0S*(acc[mt][nf][1] + by));
                float v2 = __sinf(W0S*(acc[mt][nf][2] + bx));
                float v3 = __sinf(W0S*(acc[mt][nf][3] + by));
                unsigned h0 = pack_bf2(v1, v0);
                unsigned l0 = pack_bf2(v1 - bfhi(h0), v0 - bflo(h0));
                unsigned h1 = pack_bf2(v3, v2);
                unsigned l1 = pack_bf2(v3 - bfhi(h1), v2 - bflo(h1));
                unsigned off0 = (unsigned)(r0*512)     + (unsigned)(((((nb>>3)+nf) ^ (r0 & 7))) << 4)      + tig*4;
                unsigned off1 = (unsigned)((r0+8)*512) + (unsigned)(((((nb>>3)+nf) ^ ((r0+8) & 7))) << 4) + tig*4;
                *(unsigned*)(smp + A_HI + off0) = h0;
                *(unsigned*)(smp + A_LO + off0) = l0;
                *(unsigned*)(smp + A_HI + off1) = h1;
                *(unsigned*)(smp + A_LO + off1) = l1;
            } else {
                outp[(size_t)n*P_TOT     + r0]     = acc[mt][nf][0] + bx;
                outp[(size_t)(n+1)*P_TOT + r0]     = acc[mt][nf][1] + by;
                outp[(size_t)n*P_TOT     + r0 + 8] = acc[mt][nf][2] + bx;
                outp[(size_t)(n+1)*P_TOT + r0 + 8] = acc[mt][nf][3] + by;
            }
        }
    }
}

__global__ void __launch_bounds__(NTHR)
mlp_mma_kernel(const float* __restrict__ feat, const float* __restrict__ times,
               const float* __restrict__ b0, const float* __restrict__ b1,
               const float* __restrict__ b2, const float* __restrict__ b3,
               const float* __restrict__ b4, const float* __restrict__ b5,
               float* __restrict__ out)
{
    extern __shared__ char smp[];
    float* sb = (float*)(smp + SB_OFF);
    const unsigned smb = s2u(smp);
    const int tid = threadIdx.x;
    const int wid = tid >> 5;
    const int wm  = wid & 3;          /* M warp: rows wm*32 .. +31 */
    const int wn  = wid >> 2;         /* N warp group (0/1) */
    const int rowbase = wm*32;

    const int tile = blockIdx.x;
    const int img  = tile / TILES_PER_IMG;
    const int p0   = (tile - img*TILES_PER_IMG) * MROWS;
    const int cidx = img >> 1, bidx = img & 1;
    const float tval = times[cidx];

    /* biases */
    if (tid < 64){ sb[tid] = b0[tid]; sb[64+tid] = b1[tid]; sb[896+tid] = b5[tid]; }
    for (int i = tid; i < 256; i += NTHR){ sb[128+i] = b2[i]; sb[384+i] = b3[i]; sb[640+i] = b4[i]; }

    /* stage L0 chunk0 while we build A */
    stage(smb + WB0, (const char*)g_w, 8192, tid);
    cp_commit();

    /* build A0: rows = pixels, cols 0..63 = feat channels, 64 = t, 65..95 = 0 */
    {
        const int m = tid & 127;
        const int g = tid >> 7;
        const float* fb = feat + (size_t)(bidx*64)*P_TOT + p0 + m;
#pragma unroll 4
        for (int i = 0; i < 32; i++){
            int ch = g*32 + i;
            float v = fb[(size_t)ch*P_TOT];
            __nv_bfloat16 h = __float2bfloat16(v);
            float hf = __bfloat162float(h);
            __nv_bfloat16 lo = __float2bfloat16(v - hf);
            unsigned off = (unsigned)(m*512) + (unsigned)((((ch>>3) ^ (m & 7))) << 4) + (ch & 7)*2;
            *(__nv_bfloat16*)(smp + A_HI + off) = h;
            *(__nv_bfloat16*)(smp + A_LO + off) = lo;
        }
#pragma unroll
        for (int i = 0; i < 16; i++){
            int ch = 64 + g*16 + i;
            float v = (ch == 64) ? tval : 0.0f;
            __nv_bfloat16 h = __float2bfloat16(v);
            __nv_bfloat16 lo = __float2bfloat16(v - __bfloat162float(h));
            unsigned off = (unsigned)(m*512) + (unsigned)((((ch>>3) ^ (m & 7))) << 4) + (ch & 7)*2;
            *(__nv_bfloat16*)(smp + A_HI + off) = h;
            *(__nv_bfloat16*)(smp + A_LO + off) = lo;
        }
    }

    float* outp = out + (size_t)img*64*P_TOT + p0;
    const char* gw = (const char*)g_w;
    int buf = 0;

    /* GOFF bytes = elem offsets * 2 */
    do_layer< 4,false>(smb, smp, gw +      0, 3,  8192, sb +   0, gw +  24576,  8192, buf, tid, rowbase, wn*32,  outp);
    do_layer< 4,false>(smb, smp, gw +  24576, 2,  8192, sb +  64, gw +  40960, 32768, buf, tid, rowbase, wn*32,  outp);
    do_layer<16,false>(smb, smp, gw +  40960, 2, 32768, sb + 128, gw + 106496, 32768, buf, tid, rowbase, wn*128, outp);
    do_layer<16,false>(smb, smp, gw + 106496, 8, 32768, sb + 384, gw + 368640, 32768, buf, tid, rowbase, wn*128, outp);
    do_layer<16,false>(smb, smp, gw + 368640, 8, 32768, sb + 640, gw + 630784,  8192, buf, tid, rowbase, wn*128, outp);
    do_layer< 4,true >(smb, smp, gw + 630784, 8,  8192, sb + 896, (const char*)0, 0, buf, tid, rowbase, wn*32,  outp);
}

extern "C" void kernel_launch(void* const* d_in, const int* in_sizes, int n_in,
                              void* d_out, int out_size)
{
    const float* feat  = (const float*)d_in[0];
    const float* times = (const float*)d_in[1];
    const float* w0 = (const float*)d_in[2];
    const float* b0 = (const float*)d_in[3];
    const float* w1 = (const float*)d_in[4];
    const float* b1 = (const float*)d_in[5];
    const float* w2 = (const float*)d_in[6];
    const float* b2 = (const float*)d_in[7];
    const float* w3 = (const float*)d_in[8];
    const float* b3 = (const float*)d_in[9];
    const float* w4 = (const float*)d_in[10];
    const float* b4 = (const float*)d_in[11];
    const float* w5 = (const float*)d_in[12];
    const float* b5 = (const float*)d_in[13];
    float* out = (float*)d_out;

    cudaFuncSetAttribute(mlp_mma_kernel, cudaFuncAttributeMaxDynamicSharedMemorySize, SMEM_TOT);

    prep_kernel<<<dim3(64, 6), 256>>>(w0, w1, w2, w3, w4, w5);
    mlp_mma_kernel<<<NCTA, NTHR, SMEM_TOT>>>(feat, times, b0, b1, b2, b3, b4, b5, out);
}

// round 10
// speedup vs baseline: 3.6751x; 1.0017x over previous
#include <cuda_runtime.h>
#include <cuda_bf16.h>

#define P_TOT   61440
#define MROWS   128
#define NTHR    256
#define TILES_PER_IMG 480
#define NCTA    2880
#define W0S     30.0f

/* smem map (bytes) */
#define A_HI    0          /* 128 x 256 bf16, swizzled, 64KB */
#define A_LO    65536      /* 64KB */
#define WB0     131072     /* 32KB */
#define WB1     163840     /* 32KB */
#define SB_OFF  196608     /* 960 floats */
#define SMEM_TOT 200448

/* weights, hi/lo split, per-chunk layout: [hi: N x 32 bf16 swz][lo: same] */
static __device__ __align__(16) __nv_bfloat16 g_w[348160];

__global__ void prep_kernel(const float* __restrict__ w0, const float* __restrict__ w1,
                            const float* __restrict__ w2, const float* __restrict__ w3,
                            const float* __restrict__ w4, const float* __restrict__ w5)
{
    const int K[6]    = {65,64,64,256,256,256};
    const int N[6]    = {64,64,256,256,256,64};
    const int NCHK[6] = {3,2,2,8,8,8};
    const int GOFF[6] = {0,12288,20480,53248,184320,315392};
    int l = blockIdx.y;
    const float* w = (l==0)?w0:(l==1)?w1:(l==2)?w2:(l==3)?w3:(l==4)?w4:w5;
    int Nl = N[l], Kl = K[l];
    int total = NCHK[l]*Nl*32;
    for (int idx = blockIdx.x*blockDim.x + threadIdx.x; idx < total; idx += gridDim.x*blockDim.x){
        int kin = idx & 31;
        int n   = (idx >> 5) % Nl;
        int c   = idx / (32*Nl);
        int k   = c*32 + kin;
        float v = (k < Kl) ? w[n*Kl + k] : 0.0f;
        __nv_bfloat16 h  = __float2bfloat16(v);
        __nv_bfloat16 lo = __float2bfloat16(v - __bfloat162float(h));
        /* within chunk: row n (64B), 16B-chunk swizzle c16' = c16 ^ ((n>>1)&3) */
        int eoff = n*32 + ((((kin>>3) ^ ((n>>1)&3)) << 3) | (kin & 7));
        int base = GOFF[l] + c*(Nl*64);
        g_w[base + eoff]        = h;
        g_w[base + Nl*32 + eoff] = lo;
    }
}

/* ---------------- helpers ---------------- */
__device__ __forceinline__ unsigned s2u(const void* p){
    unsigned a;
    asm("{ .reg .u64 t; cvta.to.shared.u64 t, %1; cvt.u32.u64 %0, t; }" : "=r"(a) : "l"(p));
    return a;
}
__device__ __forceinline__ void cp16(unsigned dst, const void* src){
    asm volatile("cp.async.cg.shared.global [%0], [%1], 16;" :: "r"(dst), "l"(src));
}
__device__ __forceinline__ void cp_commit(){ asm volatile("cp.async.commit_group;"); }
__device__ __forceinline__ void cp_wait0(){ asm volatile("cp.async.wait_group 0;"); }
__device__ __forceinline__ void stage(unsigned dst, const char* src, int bytes, int tid){
    for (int i = tid*16; i < bytes; i += NTHR*16) cp16(dst + i, src + i);
}
__device__ __forceinline__ void ldmx4(unsigned* r, unsigned addr){
    asm volatile("ldmatrix.sync.aligned.m8n8.x4.shared.b16 {%0,%1,%2,%3}, [%4];"
        : "=r"(r[0]), "=r"(r[1]), "=r"(r[2]), "=r"(r[3]) : "r"(addr));
}
__device__ __forceinline__ void mma_bf16(float& c0, float& c1, float& c2, float& c3,
                                         unsigned a0, unsigned a1, unsigned a2, unsigned a3,
                                         unsigned b0, unsigned b1){
    asm volatile("mma.sync.aligned.m16n8k16.row.col.f32.bf16.bf16.f32 "
        "{%0,%1,%2,%3}, {%4,%5,%6,%7}, {%8,%9}, {%0,%1,%2,%3};"
        : "+f"(c0), "+f"(c1), "+f"(c2), "+f"(c3)
        : "r"(a0), "r"(a1), "r"(a2), "r"(a3), "r"(b0), "r"(b1));
}
__device__ __forceinline__ unsigned pack_bf2(float hi_val, float lo_val){
    unsigned r;  /* d.lo = lo_val, d.hi = hi_val */
    asm("cvt.rn.bf16x2.f32 %0, %1, %2;" : "=r"(r) : "f"(hi_val), "f"(lo_val));
    return r;
}
__device__ __forceinline__ float bflo(unsigned u){ return __bfloat162float(((__nv_bfloat162*)&u)->x); }
__device__ __forceinline__ float bfhi(unsigned u){ return __bfloat162float(((__nv_bfloat162*)&u)->y); }

/* one dense layer; A in smem (hi/lo, swizzled), updated in place by epilogue */
template<int NFRAG, bool LAST>
__device__ __forceinline__ void do_layer(unsigned smb, char* smp,
    const char* gw, int nchk, int chunk_bytes, const float* sbL,
    const char* gw_next, int next_bytes, int& buf,
    int tid, int rowbase, int nb, float* outp)
{
    const int lane  = tid & 31;
    const int gid   = lane >> 2, tig = lane & 3;
    const int row_a = (lane & 7) + ((lane >> 3) & 1)*8;
    const int ca    = lane >> 4;
    const int n_off = (lane & 7) + (lane >> 4)*8;
    const int cb    = (lane >> 3) & 1;
    const int NLOC  = chunk_bytes >> 7;

    float acc[2][NFRAG][4];
#pragma unroll
    for (int i = 0; i < 2; i++)
#pragma unroll
        for (int j = 0; j < NFRAG; j++)
#pragma unroll
            for (int q = 0; q < 4; q++) acc[i][j][q] = 0.0f;

    int cur = buf;
    for (int c = 0; c < nchk; c++){
        cp_wait0();
        __syncthreads();
        if (c + 1 < nchk){
            stage(smb + (cur ? WB0 : WB1), gw + (size_t)(c+1)*chunk_bytes, chunk_bytes, tid);
            cp_commit();
        }
        unsigned wb  = smb + (cur ? WB1 : WB0);
        unsigned wlo = wb + (unsigned)(NLOC*64);
#pragma unroll
        for (int s = 0; s < 2; s++){
            const int ks = c*2 + s;
            unsigned ah[2][4], al[2][4];
#pragma unroll
            for (int mt = 0; mt < 2; mt++){
                int row = rowbase + mt*16 + row_a;
                unsigned off = (unsigned)(row*512) + (unsigned)((((ks*2 + ca) ^ (row & 7))) << 4);
                ldmx4(ah[mt], smb + A_HI + off);
                ldmx4(al[mt], smb + A_LO + off);
            }
#pragma unroll
            for (int np = 0; np < NFRAG/2; np++){
                int n = nb + np*16 + n_off;
                unsigned off = (unsigned)(n*64) + (unsigned)((((2*s + cb) ^ ((n >> 1) & 3))) << 4);
                unsigned bh[4], bl[4];
                ldmx4(bh, wb + off);
                ldmx4(bl, wlo + off);
#pragma unroll
                for (int mt = 0; mt < 2; mt++){
                    mma_bf16(acc[mt][2*np][0],acc[mt][2*np][1],acc[mt][2*np][2],acc[mt][2*np][3],
                             ah[mt][0],ah[mt][1],ah[mt][2],ah[mt][3], bh[0],bh[1]);
                    mma_bf16(acc[mt][2*np][0],acc[mt][2*np][1],acc[mt][2*np][2],acc[mt][2*np][3],
                             al[mt][0],al[mt][1],al[mt][2],al[mt][3], bh[0],bh[1]);
                    mma_bf16(acc[mt][2*np][0],acc[mt][2*np][1],acc[mt][2*np][2],acc[mt][2*np][3],
                             ah[mt][0],ah[mt][1],ah[mt][2],ah[mt][3], bl[0],bl[1]);
                    mma_bf16(acc[mt][2*np+1][0],acc[mt][2*np+1][1],acc[mt][2*np+1][2],acc[mt][2*np+1][3],
                             ah[mt][0],ah[mt][1],ah[mt][2],ah[mt][3], bh[2],bh[3]);
                    mma_bf16(acc[mt][2*np+1][0],acc[mt][2*np+1][1],acc[mt][2*np+1][2],acc[mt][2*np+1][3],
                             al[mt][0],al[mt][1],al[mt][2],al[mt][3], bh[2],bh[3]);
                    mma_bf16(acc[mt][2*np+1][0],acc[mt][2*np+1][1],acc[mt][2*np+1][2],acc[mt][2*np+1][3],
                             ah[mt][0],ah[mt][1],ah[mt][2],ah[mt][3], bl[2],bl[3]);
                }
            }
        }
        cur ^= 1;
    }
    buf = cur;
    __syncthreads();           /* all A reads done before epilogue overwrites */
    if (gw_next){
        stage(smb + (cur ? WB1 : WB0), gw_next, next_bytes, tid);
        cp_commit();
    }

#pragma unroll
    for (int mt = 0; mt < 2; mt++){
#pragma unroll
        for (int nf = 0; nf < NFRAG; nf++){
            int n = nb + nf*8 + 2*tig;
            float bx = sbL[n], by = sbL[n+1];
            int r0 = rowbase + mt*16 + gid;
            if (!LAST){
                float v0 = __sinf(W0S*(acc[mt][nf][0] + bx));
                float v1 = __sinf(W0S*(acc[mt][nf][1] + by));
                float v2 = __sinf(W0S*(acc[mt][nf][2] + bx));
                float v3 = __sinf(W0S*(acc[mt][nf][3] + by));
                unsigned h0 = pack_bf2(v1, v0);
                unsigned l0 = pack_bf2(v1 - bfhi(h0), v0 - bflo(h0));
                unsigned h1 = pack_bf2(v3, v2);
                unsigned l1 = pack_bf2(v3 - bfhi(h1), v2 - bflo(h1));
                unsigned off0 = (unsigned)(r0*512)     + (unsigned)(((((nb>>3)+nf) ^ (r0 & 7))) << 4)      + tig*4;
                unsigned off1 = (unsigned)((r0+8)*512) + (unsigned)(((((nb>>3)+nf) ^ ((r0+8) & 7))) << 4) + tig*4;
                *(unsigned*)(smp + A_HI + off0) = h0;
                *(unsigned*)(smp + A_LO + off0) = l0;
                *(unsigned*)(smp + A_HI + off1) = h1;
                *(unsigned*)(smp + A_LO + off1) = l1;
            } else {
                outp[(size_t)n*P_TOT     + r0]     = acc[mt][nf][0] + bx;
                outp[(size_t)(n+1)*P_TOT + r0]     = acc[mt][nf][1] + by;
                outp[(size_t)n*P_TOT     + r0 + 8] = acc[mt][nf][2] + bx;
                outp[(size_t)(n+1)*P_TOT + r0 + 8] = acc[mt][nf][3] + by;
            }
        }
    }
}

__global__ void __launch_bounds__(NTHR)
mlp_mma_kernel(const float* __restrict__ feat, const float* __restrict__ times,
               const float* __restrict__ b0, const float* __restrict__ b1,
               const float* __restrict__ b2, const float* __restrict__ b3,
               const float* __restrict__ b4, const float* __restrict__ b5,
               float* __restrict__ out)
{
    extern __shared__ char smp[];
    float* sb = (float*)(smp + SB_OFF);
    const unsigned smb = s2u(smp);
    const int tid = threadIdx.x;
    const int wid = tid >> 5;
    const int wm  = wid & 3;          /* M warp: rows wm*32 .. +31 */
    const int wn  = wid >> 2;         /* N warp group (0/1) */
    const int rowbase = wm*32;

    const int tile = blockIdx.x;
    const int img  = tile / TILES_PER_IMG;
    const int p0   = (tile - img*TILES_PER_IMG) * MROWS;
    const int cidx = img >> 1, bidx = img & 1;
    const float tval = times[cidx];

    /* biases */
    if (tid < 64){ sb[tid] = b0[tid]; sb[64+tid] = b1[tid]; sb[896+tid] = b5[tid]; }
    for (int i = tid; i < 256; i += NTHR){ sb[128+i] = b2[i]; sb[384+i] = b3[i]; sb[640+i] = b4[i]; }

    /* stage L0 chunk0 while we build A */
    stage(smb + WB0, (const char*)g_w, 8192, tid);
    cp_commit();

    /* build A0: rows = pixels, cols 0..63 = feat channels, 64 = t, 65..95 = 0 */
    {
        const int m = tid & 127;
        const int g = tid >> 7;
        const float* fb = feat + (size_t)(bidx*64)*P_TOT + p0 + m;
#pragma unroll 4
        for (int i = 0; i < 32; i++){
            int ch = g*32 + i;
            float v = fb[(size_t)ch*P_TOT];
            __nv_bfloat16 h = __float2bfloat16(v);
            float hf = __bfloat162float(h);
            __nv_bfloat16 lo = __float2bfloat16(v - hf);
            unsigned off = (unsigned)(m*512) + (unsigned)((((ch>>3) ^ (m & 7))) << 4) + (ch & 7)*2;
            *(__nv_bfloat16*)(smp + A_HI + off) = h;
            *(__nv_bfloat16*)(smp + A_LO + off) = lo;
        }
#pragma unroll
        for (int i = 0; i < 16; i++){
            int ch = 64 + g*16 + i;
            float v = (ch == 64) ? tval : 0.0f;
            __nv_bfloat16 h = __float2bfloat16(v);
            __nv_bfloat16 lo = __float2bfloat16(v - __bfloat162float(h));
            unsigned off = (unsigned)(m*512) + (unsigned)((((ch>>3) ^ (m & 7))) << 4) + (ch & 7)*2;
            *(__nv_bfloat16*)(smp + A_HI + off) = h;
            *(__nv_bfloat16*)(smp + A_LO + off) = lo;
        }
    }

    float* outp = out + (size_t)img*64*P_TOT + p0;
    const char* gw = (const char*)g_w;
    int buf = 0;

    /* GOFF bytes = elem offsets * 2 */
    do_layer< 4,false>(smb, smp, gw +      0, 3,  8192, sb +   0, gw +  24576,  8192, buf, tid, rowbase, wn*32,  outp);
    do_layer< 4,false>(smb, smp, gw +  24576, 2,  8192, sb +  64, gw +  40960, 32768, buf, tid, rowbase, wn*32,  outp);
    do_layer<16,false>(smb, smp, gw +  40960, 2, 32768, sb + 128, gw + 106496, 32768, buf, tid, rowbase, wn*128, outp);
    do_layer<16,false>(smb, smp, gw + 106496, 8, 32768, sb + 384, gw + 368640, 32768, buf, tid, rowbase, wn*128, outp);
    do_layer<16,false>(smb, smp, gw + 368640, 8, 32768, sb + 640, gw + 630784,  8192, buf, tid, rowbase, wn*128, outp);
    do_layer< 4,true >(smb, smp, gw + 630784, 8,  8192, sb + 896, (const char*)0, 0, buf, tid, rowbase, wn*32,  outp);
}

extern "C" void kernel_launch(void* const* d_in, const int* in_sizes, int n_in,
                              void* d_out, int out_size)
{
    const float* feat  = (const float*)d_in[0];
    const float* times = (const float*)d_in[1];
    const float* w0 = (const float*)d_in[2];
    const float* b0 = (const float*)d_in[3];
    const float* w1 = (const float*)d_in[4];
    const float* b1 = (const float*)d_in[5];
    const float* w2 = (const float*)d_in[6];
    const float* b2 = (const float*)d_in[7];
    const float* w3 = (const float*)d_in[8];
    const float* b3 = (const float*)d_in[9];
    const float* w4 = (const float*)d_in[10];
    const float* b4 = (const float*)d_in[11];
    const float* w5 = (const float*)d_in[12];
    const float* b5 = (const float*)d_in[13];
    float* out = (float*)d_out;

    cudaFuncSetAttribute(mlp_mma_kernel, cudaFuncAttributeMaxDynamicSharedMemorySize, SMEM_TOT);

    prep_kernel<<<dim3(64, 6), 256>>>(w0, w1, w2, w3, w4, w5);
    mlp_mma_kernel<<<NCTA, NTHR, SMEM_TOT>>>(feat, times, b0, b1, b2, b3, b4, b5, out);
}